// round 1
// baseline (speedup 1.0000x reference)
#include <cuda_runtime.h>

#define BATCH   4
#define HEIGHT  64
#define WIDTH   64
#define CH      64
#define NGROUPS 8
#define NTOK    (HEIGHT*WIDTH)        // 4096 tokens per batch
#define ROWS    (BATCH*NTOK)          // 16384
#define EPSV    1e-5f
#define ATT_SCALE 0.125f              // 64^-0.5

// Scratch (allocation-free: __device__ globals)
__device__ float  g_xn [ROWS*CH];
__device__ float  g_q  [ROWS*CH];
__device__ float  g_k  [ROWS*CH];
__device__ float  g_v  [ROWS*CH];
__device__ float  g_att[ROWS*CH];
__device__ float2 g_stats[BATCH*NGROUPS];   // (mean, rstd)

// ---------------------------------------------------------------------------
// 1. GroupNorm statistics. Groups tile H, so each (b,g) group is a contiguous
//    slab of 8*64*64 = 32768 floats. One block per group.
// ---------------------------------------------------------------------------
__global__ void gn_stats_kernel(const float* __restrict__ x) {
    __shared__ float ssum[256];
    __shared__ float ssq [256];
    const int t = threadIdx.x;
    const float4* base = (const float4*)(x + (size_t)blockIdx.x * 32768);
    float s = 0.f, sq = 0.f;
    #pragma unroll 4
    for (int i = t; i < 8192; i += 256) {
        float4 v = base[i];
        s  += (v.x + v.y) + (v.z + v.w);
        sq += (v.x*v.x + v.y*v.y) + (v.z*v.z + v.w*v.w);
    }
    ssum[t] = s; ssq[t] = sq;
    __syncthreads();
    for (int st = 128; st > 0; st >>= 1) {
        if (t < st) { ssum[t] += ssum[t+st]; ssq[t] += ssq[t+st]; }
        __syncthreads();
    }
    if (t == 0) {
        float mean = ssum[0] * (1.f/32768.f);
        float var  = ssq[0]  * (1.f/32768.f) - mean*mean;
        g_stats[blockIdx.x] = make_float2(mean, rsqrtf(var + EPSV));
    }
}

// ---------------------------------------------------------------------------
// 2. Apply normalization. NOTE: gamma/beta are indexed by H (dim 1), per the
//    reference (GroupNorm treats height as the channel axis).
// ---------------------------------------------------------------------------
__global__ void gn_apply_kernel(const float* __restrict__ x,
                                const float* __restrict__ gamma,
                                const float* __restrict__ beta) {
    int i = blockIdx.x * blockDim.x + threadIdx.x;   // float4 index, grid sized exactly
    int e = i << 2;                                  // element index
    int h = (e >> 12) & 63;                          // e / (W*C) % H
    int sidx = (e >> 18) * NGROUPS + (h >> 3);       // b*8 + h/8
    float2 st = g_stats[sidx];
    float g  = gamma[h] * st.y;
    float bt = beta[h] - st.x * g;
    float4 v = ((const float4*)x)[i];
    float4 r;
    r.x = v.x*g + bt; r.y = v.y*g + bt; r.z = v.z*g + bt; r.w = v.w*g + bt;
    ((float4*)g_xn)[i] = r;
}

// ---------------------------------------------------------------------------
// 3. Row-parallel 64x64 linear: out = in @ W + b. One warp per row; lane
//    computes output cols (lane, lane+32). W resident in smem.
// ---------------------------------------------------------------------------
__global__ void linear64_kernel(const float* __restrict__ in,
                                const float* __restrict__ W,
                                const float* __restrict__ bias,
                                float* __restrict__ out) {
    __shared__ float sW[64*64];
    __shared__ float sB[64];
    __shared__ float sX[8][64];
    const int t = threadIdx.x;
    for (int i = t; i < 4096; i += 256) sW[i] = W[i];
    if (t < 64) sB[t] = bias[t];
    __syncthreads();
    const int w = t >> 5, lane = t & 31;
    for (int row = blockIdx.x * 8 + w; row < ROWS; row += gridDim.x * 8) {
        sX[w][lane]      = in[row*64 + lane];
        sX[w][lane + 32] = in[row*64 + lane + 32];
        __syncwarp();
        float a0 = sB[lane], a1 = sB[lane + 32];
        #pragma unroll
        for (int c = 0; c < 64; c++) {
            float xv = sX[w][c];
            a0 = fmaf(xv, sW[c*64 + lane],      a0);
            a1 = fmaf(xv, sW[c*64 + lane + 32], a1);
        }
        out[row*64 + lane]      = a0;
        out[row*64 + lane + 32] = a1;
        __syncwarp();
    }
}

// ---------------------------------------------------------------------------
// 4. Flash attention, fp32 SIMT. One query per thread (q,o in registers),
//    K/V tiles of 32 keys staged in smem (broadcast reads). Tile-granular
//    online-softmax rescale.
// ---------------------------------------------------------------------------
#define QT 64   // queries (threads) per block
#define KT 32   // keys per tile

__global__ __launch_bounds__(QT) void attn_kernel(float* __restrict__ out) {
    __shared__ float sK[KT*64];
    __shared__ float sV[KT*64];

    const int b    = blockIdx.x / (NTOK / QT);
    const int qrow = (blockIdx.x % (NTOK / QT)) * QT + threadIdx.x;
    const float* qb = g_q + ((size_t)b * NTOK + qrow) * 64;
    const float* kb = g_k + (size_t)b * NTOK * 64;
    const float* vb = g_v + (size_t)b * NTOK * 64;

    float qr[64];
    #pragma unroll
    for (int i = 0; i < 16; i++) {
        float4 v = ((const float4*)qb)[i];
        qr[4*i+0] = v.x * ATT_SCALE; qr[4*i+1] = v.y * ATT_SCALE;
        qr[4*i+2] = v.z * ATT_SCALE; qr[4*i+3] = v.w * ATT_SCALE;
    }
    float o[64];
    #pragma unroll
    for (int d = 0; d < 64; d++) o[d] = 0.f;
    float m = -1e30f, l = 0.f;

    for (int kt = 0; kt < NTOK; kt += KT) {
        // cooperative tile load: 2048 floats each = 8 float4 per thread
        const float4* ks = (const float4*)(kb + kt*64);
        const float4* vs = (const float4*)(vb + kt*64);
        float4* sk4 = (float4*)sK;
        float4* sv4 = (float4*)sV;
        #pragma unroll
        for (int i = 0; i < 8; i++) {
            sk4[threadIdx.x + i*QT] = ks[threadIdx.x + i*QT];
            sv4[threadIdx.x + i*QT] = vs[threadIdx.x + i*QT];
        }
        __syncthreads();

        float s[KT];
        float tmax = -1e30f;
        #pragma unroll 2
        for (int j = 0; j < KT; j++) {
            float a0 = 0.f, a1 = 0.f, a2 = 0.f, a3 = 0.f;
            const float* kr = sK + j*64;
            #pragma unroll
            for (int d = 0; d < 64; d += 4) {
                a0 = fmaf(qr[d+0], kr[d+0], a0);
                a1 = fmaf(qr[d+1], kr[d+1], a1);
                a2 = fmaf(qr[d+2], kr[d+2], a2);
                a3 = fmaf(qr[d+3], kr[d+3], a3);
            }
            s[j] = (a0 + a1) + (a2 + a3);
            tmax = fmaxf(tmax, s[j]);
        }

        float mnew = fmaxf(m, tmax);
        float corr = __expf(m - mnew);
        l *= corr;
        #pragma unroll
        for (int d = 0; d < 64; d++) o[d] *= corr;

        #pragma unroll 2
        for (int j = 0; j < KT; j++) {
            float p = __expf(s[j] - mnew);
            l += p;
            const float* vr = sV + j*64;
            #pragma unroll
            for (int d = 0; d < 64; d++) o[d] = fmaf(p, vr[d], o[d]);
        }
        m = mnew;
        __syncthreads();
    }

    float inv = 1.f / l;
    float* ob = out + ((size_t)b * NTOK + qrow) * 64;
    #pragma unroll
    for (int i = 0; i < 16; i++) {
        float4 r;
        r.x = o[4*i+0]*inv; r.y = o[4*i+1]*inv;
        r.z = o[4*i+2]*inv; r.w = o[4*i+3]*inv;
        ((float4*)ob)[i] = r;
    }
}

// ---------------------------------------------------------------------------
// 5. Output projection + residual: out = xn + att @ Wo + bo
// ---------------------------------------------------------------------------
__global__ void linear_final_kernel(const float* __restrict__ in,
                                    const float* __restrict__ W,
                                    const float* __restrict__ bias,
                                    const float* __restrict__ res,
                                    float* __restrict__ out) {
    __shared__ float sW[64*64];
    __shared__ float sB[64];
    __shared__ float sX[8][64];
    const int t = threadIdx.x;
    for (int i = t; i < 4096; i += 256) sW[i] = W[i];
    if (t < 64) sB[t] = bias[t];
    __syncthreads();
    const int w = t >> 5, lane = t & 31;
    for (int row = blockIdx.x * 8 + w; row < ROWS; row += gridDim.x * 8) {
        sX[w][lane]      = in[row*64 + lane];
        sX[w][lane + 32] = in[row*64 + lane + 32];
        __syncwarp();
        float a0 = sB[lane], a1 = sB[lane + 32];
        #pragma unroll
        for (int c = 0; c < 64; c++) {
            float xv = sX[w][c];
            a0 = fmaf(xv, sW[c*64 + lane],      a0);
            a1 = fmaf(xv, sW[c*64 + lane + 32], a1);
        }
        out[row*64 + lane]      = res[row*64 + lane]      + a0;
        out[row*64 + lane + 32] = res[row*64 + lane + 32] + a1;
        __syncwarp();
    }
}

// ---------------------------------------------------------------------------
extern "C" void kernel_launch(void* const* d_in, const int* in_sizes, int n_in,
                              void* d_out, int out_size) {
    const float* x     = (const float*)d_in[0];
    const float* gamma = (const float*)d_in[1];
    const float* beta  = (const float*)d_in[2];
    const float* Wq    = (const float*)d_in[3];
    const float* bq    = (const float*)d_in[4];
    const float* Wk    = (const float*)d_in[5];
    const float* bk    = (const float*)d_in[6];
    const float* Wv    = (const float*)d_in[7];
    const float* bv    = (const float*)d_in[8];
    const float* Wo    = (const float*)d_in[9];
    const float* bo    = (const float*)d_in[10];
    float* out = (float*)d_out;

    float *xn, *q, *k, *v, *att;
    cudaGetSymbolAddress((void**)&xn,  g_xn);
    cudaGetSymbolAddress((void**)&q,   g_q);
    cudaGetSymbolAddress((void**)&k,   g_k);
    cudaGetSymbolAddress((void**)&v,   g_v);
    cudaGetSymbolAddress((void**)&att, g_att);

    gn_stats_kernel<<<BATCH*NGROUPS, 256>>>(x);
    gn_apply_kernel<<<(ROWS*CH/4)/256, 256>>>(x, gamma, beta);
    linear64_kernel<<<128, 256>>>(xn, Wq, bq, q);
    linear64_kernel<<<128, 256>>>(xn, Wk, bk, k);
    linear64_kernel<<<128, 256>>>(xn, Wv, bv, v);
    attn_kernel<<<BATCH*(NTOK/QT), QT>>>(att);
    linear_final_kernel<<<128, 256>>>(att, Wo, bo, xn, out);
}

// round 2
// speedup vs baseline: 3.5666x; 3.5666x over previous
#include <cuda_runtime.h>

#define BATCH   4
#define NTOK    4096
#define ROWS    16384
#define EPSV    1e-5f
#define ATT_SCALE 0.125f
#define SKS 68   // smem stride (floats) for K and S tiles
#define SVS 72   // smem stride for V tile (conflict-free PV b-frags)

// Scratch (allocation-free: __device__ globals)
__device__ float  g_xn [ROWS*64];
__device__ float  g_q  [ROWS*64];
__device__ float  g_k  [ROWS*64];
__device__ float  g_v  [ROWS*64];
__device__ float  g_att[ROWS*64];
__device__ float2 g_part[256];
__device__ float2 g_stats[32];   // (mean, rstd) per (b, group)

__device__ __forceinline__ unsigned f2tf32(float f) {
    unsigned u; asm("cvt.rna.tf32.f32 %0, %1;" : "=r"(u) : "f"(f)); return u;
}
__device__ __forceinline__ void mma_tf32(float c[4], unsigned a0, unsigned a1,
                                         unsigned a2, unsigned a3,
                                         unsigned b0, unsigned b1) {
    asm volatile(
        "mma.sync.aligned.m16n8k8.row.col.f32.tf32.tf32.f32 "
        "{%0,%1,%2,%3}, {%4,%5,%6,%7}, {%8,%9}, {%0,%1,%2,%3};"
        : "+f"(c[0]), "+f"(c[1]), "+f"(c[2]), "+f"(c[3])
        : "r"(a0), "r"(a1), "r"(a2), "r"(a3), "r"(b0), "r"(b1));
}

// ---------------------------------------------------------------------------
// 1a. GroupNorm partial sums: 8 blocks per (b,group), 256 blocks total.
// ---------------------------------------------------------------------------
__global__ void gn_stats_part(const float* __restrict__ x) {
    __shared__ float ss[256], sq[256];
    const int t = threadIdx.x;
    const float4* base = (const float4*)x + (size_t)blockIdx.x * 1024;
    float s = 0.f, q = 0.f;
    #pragma unroll
    for (int i = 0; i < 4; i++) {
        float4 v = base[t + i*256];
        s += (v.x + v.y) + (v.z + v.w);
        q += (v.x*v.x + v.y*v.y) + (v.z*v.z + v.w*v.w);
    }
    ss[t] = s; sq[t] = q;
    __syncthreads();
    for (int st = 128; st; st >>= 1) {
        if (t < st) { ss[t] += ss[t+st]; sq[t] += sq[t+st]; }
        __syncthreads();
    }
    if (!t) g_part[blockIdx.x] = make_float2(ss[0], sq[0]);
}

// 1b. Finalize 32 group stats from 256 partials.
__global__ void gn_stats_final() {
    const int t = threadIdx.x;   // 32 threads
    float s = 0.f, q = 0.f;
    #pragma unroll
    for (int i = 0; i < 8; i++) { float2 p = g_part[t*8 + i]; s += p.x; q += p.y; }
    float mean = s * (1.f/32768.f);
    float var  = q * (1.f/32768.f) - mean*mean;
    g_stats[t] = make_float2(mean, rsqrtf(var + EPSV));
}

// ---------------------------------------------------------------------------
// 2. Apply normalization. gamma/beta indexed by H (dim 1 is channel axis).
// ---------------------------------------------------------------------------
__global__ void gn_apply_kernel(const float* __restrict__ x,
                                const float* __restrict__ gamma,
                                const float* __restrict__ beta) {
    int i = blockIdx.x * blockDim.x + threadIdx.x;   // float4 index
    int e = i << 2;
    int h = (e >> 12) & 63;
    int sidx = (e >> 18) * 8 + (h >> 3);
    float2 st = g_stats[sidx];
    float g  = gamma[h] * st.y;
    float bt = beta[h] - st.x * g;
    float4 v = ((const float4*)x)[i];
    float4 r;
    r.x = v.x*g + bt; r.y = v.y*g + bt; r.z = v.z*g + bt; r.w = v.w*g + bt;
    ((float4*)g_xn)[i] = r;
}

// ---------------------------------------------------------------------------
// 3. Fused QKV projection: reads xn once, 3 weight mats resident in smem.
// ---------------------------------------------------------------------------
__global__ __launch_bounds__(256) void qkv_kernel(
        const float* __restrict__ Wq, const float* __restrict__ bq,
        const float* __restrict__ Wk, const float* __restrict__ bk,
        const float* __restrict__ Wv, const float* __restrict__ bv) {
    extern __shared__ float sm[];
    float* sW = sm;            // 3*4096
    float* sB = sm + 12288;    // 3*64
    float* sX = sm + 12480;    // 8*64
    const int t = threadIdx.x;
    for (int i = t; i < 4096; i += 256) {
        sW[i] = Wq[i]; sW[4096+i] = Wk[i]; sW[8192+i] = Wv[i];
    }
    if (t < 64) { sB[t] = bq[t]; sB[64+t] = bk[t]; sB[128+t] = bv[t]; }
    __syncthreads();
    const int w = t >> 5, lane = t & 31;
    for (int row = blockIdx.x*8 + w; row < ROWS; row += gridDim.x*8) {
        sX[w*64 + lane]      = g_xn[row*64 + lane];
        sX[w*64 + lane + 32] = g_xn[row*64 + lane + 32];
        __syncwarp();
        float q0 = sB[lane],     q1 = sB[lane+32];
        float k0 = sB[64+lane],  k1 = sB[64+lane+32];
        float v0 = sB[128+lane], v1 = sB[128+lane+32];
        #pragma unroll
        for (int c = 0; c < 64; c++) {
            float xv = sX[w*64 + c];
            q0 = fmaf(xv, sW[c*64+lane],         q0);
            q1 = fmaf(xv, sW[c*64+lane+32],      q1);
            k0 = fmaf(xv, sW[4096+c*64+lane],    k0);
            k1 = fmaf(xv, sW[4096+c*64+lane+32], k1);
            v0 = fmaf(xv, sW[8192+c*64+lane],    v0);
            v1 = fmaf(xv, sW[8192+c*64+lane+32], v1);
        }
        g_q[row*64+lane] = q0; g_q[row*64+lane+32] = q1;
        g_k[row*64+lane] = k0; g_k[row*64+lane+32] = k1;
        g_v[row*64+lane] = v0; g_v[row*64+lane+32] = v1;
        __syncwarp();
    }
}

// ---------------------------------------------------------------------------
// 4. Flash attention on tf32 tensor cores (mma.sync m16n8k8).
//    Block = 128 queries, 8 warps (one m16 tile each). Online softmax done
//    block-wide via smem round-trip of S fragments.
// ---------------------------------------------------------------------------
__global__ __launch_bounds__(256, 1) void attn_mma_kernel(float* __restrict__ out) {
    extern __shared__ float sm[];
    float* sK = sm;            // 64*SKS  = 4352
    float* sV = sm + 4352;     // 64*SVS  = 4608
    float* sS = sm + 8960;     // 128*SKS = 8704
    float* sC = sm + 17664;    // 128 (corr / inv-l per row)

    const int tid  = threadIdx.x;
    const int warp = tid >> 5, lane = tid & 31;
    const int g = lane >> 2, t4 = lane & 3;
    const int b = blockIdx.x >> 5;
    const int qbase = (blockIdx.x & 31) * 128;
    const float* Qg = g_q + ((size_t)b*NTOK + qbase)*64;
    const float* Kg = g_k + (size_t)b*NTOK*64;
    const float* Vg = g_v + (size_t)b*NTOK*64;
    const int r0 = warp*16 + g;       // this lane's mma rows: r0 and r0+8

    // Q fragments (scaled, tf32-rounded), kept in registers for the whole block
    unsigned qa[8][4];
    #pragma unroll
    for (int ks = 0; ks < 8; ks++) {
        qa[ks][0] = f2tf32(Qg[ r0   *64 + ks*8 + t4    ] * ATT_SCALE);
        qa[ks][1] = f2tf32(Qg[(r0+8)*64 + ks*8 + t4    ] * ATT_SCALE);
        qa[ks][2] = f2tf32(Qg[ r0   *64 + ks*8 + t4 + 4] * ATT_SCALE);
        qa[ks][3] = f2tf32(Qg[(r0+8)*64 + ks*8 + t4 + 4] * ATT_SCALE);
    }
    float o[8][4];
    #pragma unroll
    for (int n = 0; n < 8; n++) o[n][0] = o[n][1] = o[n][2] = o[n][3] = 0.f;

    // online-softmax state: thread pair (tid, tid^1) owns row tid>>1
    float m = -1e30f, l = 0.f;
    const int srow = tid >> 1, shalf = (tid & 1) * 32;

    for (int kt = 0; kt < NTOK; kt += 64) {
        // cooperative K/V tile load (tf32-rounded at store)
        const float4* kg4 = (const float4*)(Kg + kt*64);
        const float4* vg4 = (const float4*)(Vg + kt*64);
        #pragma unroll
        for (int i = 0; i < 4; i++) {
            int idx = tid + i*256;
            int row = idx >> 4, c4 = (idx & 15) * 4;
            float4 kv = kg4[idx];
            uint4 ku; ku.x=f2tf32(kv.x); ku.y=f2tf32(kv.y); ku.z=f2tf32(kv.z); ku.w=f2tf32(kv.w);
            *(uint4*)&sK[row*SKS + c4] = ku;
            float4 vv = vg4[idx];
            uint4 vu; vu.x=f2tf32(vv.x); vu.y=f2tf32(vv.y); vu.z=f2tf32(vv.z); vu.w=f2tf32(vv.w);
            *(uint4*)&sV[row*SVS + c4] = vu;
        }
        __syncthreads();

        // S = Q @ K^T  (64 mma per warp)
        float sacc[8][4];
        #pragma unroll
        for (int n = 0; n < 8; n++) sacc[n][0]=sacc[n][1]=sacc[n][2]=sacc[n][3]=0.f;
        #pragma unroll
        for (int ks = 0; ks < 8; ks++) {
            #pragma unroll
            for (int nt = 0; nt < 8; nt++) {
                unsigned b0 = __float_as_uint(sK[(nt*8+g)*SKS + ks*8 + t4    ]);
                unsigned b1 = __float_as_uint(sK[(nt*8+g)*SKS + ks*8 + t4 + 4]);
                mma_tf32(sacc[nt], qa[ks][0], qa[ks][1], qa[ks][2], qa[ks][3], b0, b1);
            }
        }
        // spill S fragments to smem for row-wise softmax
        #pragma unroll
        for (int nt = 0; nt < 8; nt++) {
            *(float2*)&sS[ r0   *SKS + nt*8 + 2*t4] = make_float2(sacc[nt][0], sacc[nt][1]);
            *(float2*)&sS[(r0+8)*SKS + nt*8 + 2*t4] = make_float2(sacc[nt][2], sacc[nt][3]);
        }
        __syncthreads();

        // online softmax: each thread handles half a row (32 cols)
        {
            float4* sp = (float4*)(sS + srow*SKS + shalf);
            float4 vv[8];
            float tmax = -1e30f;
            #pragma unroll
            for (int j = 0; j < 8; j++) {
                vv[j] = sp[j];
                tmax = fmaxf(tmax, fmaxf(fmaxf(vv[j].x, vv[j].y), fmaxf(vv[j].z, vv[j].w)));
            }
            tmax = fmaxf(tmax, __shfl_xor_sync(0xffffffffu, tmax, 1));
            float mnew = fmaxf(m, tmax);
            float corr = __expf(m - mnew);
            float ls = 0.f;
            #pragma unroll
            for (int j = 0; j < 8; j++) {
                float4 p;
                p.x = __uint_as_float(f2tf32(__expf(vv[j].x - mnew)));
                p.y = __uint_as_float(f2tf32(__expf(vv[j].y - mnew)));
                p.z = __uint_as_float(f2tf32(__expf(vv[j].z - mnew)));
                p.w = __uint_as_float(f2tf32(__expf(vv[j].w - mnew)));
                ls += (p.x + p.y) + (p.z + p.w);
                sp[j] = p;
            }
            ls += __shfl_xor_sync(0xffffffffu, ls, 1);
            l = l*corr + ls;
            m = mnew;
            if (!(tid & 1)) sC[srow] = corr;
        }
        __syncthreads();

        // rescale O by corr, then O += P @ V  (64 mma per warp)
        float c_r = sC[r0], c_r8 = sC[r0+8];
        #pragma unroll
        for (int n = 0; n < 8; n++) {
            o[n][0] *= c_r; o[n][1] *= c_r; o[n][2] *= c_r8; o[n][3] *= c_r8;
        }
        #pragma unroll
        for (int ks = 0; ks < 8; ks++) {
            unsigned a0 = __float_as_uint(sS[ r0   *SKS + ks*8 + t4    ]);
            unsigned a1 = __float_as_uint(sS[(r0+8)*SKS + ks*8 + t4    ]);
            unsigned a2 = __float_as_uint(sS[ r0   *SKS + ks*8 + t4 + 4]);
            unsigned a3 = __float_as_uint(sS[(r0+8)*SKS + ks*8 + t4 + 4]);
            #pragma unroll
            for (int nt = 0; nt < 8; nt++) {
                unsigned b0 = __float_as_uint(sV[(ks*8+t4  )*SVS + nt*8 + g]);
                unsigned b1 = __float_as_uint(sV[(ks*8+t4+4)*SVS + nt*8 + g]);
                mma_tf32(o[nt], a0, a1, a2, a3, b0, b1);
            }
        }
        __syncthreads();
    }

    // final normalization and store
    if (!(tid & 1)) sC[srow] = 1.f / l;
    __syncthreads();
    float i_r = sC[r0], i_r8 = sC[r0+8];
    float* Og = out + ((size_t)b*NTOK + qbase)*64;
    #pragma unroll
    for (int nt = 0; nt < 8; nt++) {
        *(float2*)&Og[ r0   *64 + nt*8 + 2*t4] = make_float2(o[nt][0]*i_r,  o[nt][1]*i_r);
        *(float2*)&Og[(r0+8)*64 + nt*8 + 2*t4] = make_float2(o[nt][2]*i_r8, o[nt][3]*i_r8);
    }
}

// ---------------------------------------------------------------------------
// 5. Output projection + residual: out = xn + att @ Wo + bo
// ---------------------------------------------------------------------------
__global__ __launch_bounds__(256) void linear_final_kernel(
        const float* __restrict__ in, const float* __restrict__ W,
        const float* __restrict__ bias, const float* __restrict__ res,
        float* __restrict__ out) {
    __shared__ float sW[64*64];
    __shared__ float sB[64];
    __shared__ float sX[8][64];
    const int t = threadIdx.x;
    for (int i = t; i < 4096; i += 256) sW[i] = W[i];
    if (t < 64) sB[t] = bias[t];
    __syncthreads();
    const int w = t >> 5, lane = t & 31;
    for (int row = blockIdx.x*8 + w; row < ROWS; row += gridDim.x*8) {
        sX[w][lane]      = in[row*64 + lane];
        sX[w][lane + 32] = in[row*64 + lane + 32];
        __syncwarp();
        float a0 = sB[lane], a1 = sB[lane + 32];
        #pragma unroll
        for (int c = 0; c < 64; c++) {
            float xv = sX[w][c];
            a0 = fmaf(xv, sW[c*64 + lane],      a0);
            a1 = fmaf(xv, sW[c*64 + lane + 32], a1);
        }
        out[row*64 + lane]      = res[row*64 + lane]      + a0;
        out[row*64 + lane + 32] = res[row*64 + lane + 32] + a1;
        __syncwarp();
    }
}

// ---------------------------------------------------------------------------
extern "C" void kernel_launch(void* const* d_in, const int* in_sizes, int n_in,
                              void* d_out, int out_size) {
    const float* x     = (const float*)d_in[0];
    const float* gamma = (const float*)d_in[1];
    const float* beta  = (const float*)d_in[2];
    const float* Wq    = (const float*)d_in[3];
    const float* bq    = (const float*)d_in[4];
    const float* Wk    = (const float*)d_in[5];
    const float* bk    = (const float*)d_in[6];
    const float* Wv    = (const float*)d_in[7];
    const float* bv    = (const float*)d_in[8];
    const float* Wo    = (const float*)d_in[9];
    const float* bo    = (const float*)d_in[10];
    float* out = (float*)d_out;

    float *xn, *att;
    cudaGetSymbolAddress((void**)&xn,  g_xn);
    cudaGetSymbolAddress((void**)&att, g_att);

    const int qkv_smem  = (3*4096 + 3*64 + 8*64) * 4;       // 51968 B
    const int attn_smem = (64*SKS + 64*SVS + 128*SKS + 128) * 4;  // 71168 B
    cudaFuncSetAttribute(qkv_kernel, cudaFuncAttributeMaxDynamicSharedMemorySize, qkv_smem);
    cudaFuncSetAttribute(attn_mma_kernel, cudaFuncAttributeMaxDynamicSharedMemorySize, attn_smem);

    gn_stats_part<<<256, 256>>>(x);
    gn_stats_final<<<1, 32>>>();
    gn_apply_kernel<<<1024, 256>>>(x, gamma, beta);
    qkv_kernel<<<256, 256, qkv_smem>>>(Wq, bq, Wk, bk, Wv, bv);
    attn_mma_kernel<<<128, 256, attn_smem>>>(att);
    linear_final_kernel<<<256, 256>>>(att, Wo, bo, xn, out);
}

// round 3
// speedup vs baseline: 8.9203x; 2.5011x over previous
#include <cuda_runtime.h>
#include <cuda_fp16.h>

#define NTOK 4096
#define ROWS 16384
#define EPSV 1e-5f
#define SC_L2E 0.18033688011112042f   // 0.125 * log2(e)
#define SKD 72                        // smem half-stride for K/V tiles

// Scratch (allocation-free: __device__ globals)
__device__ __align__(16) __half g_q[ROWS*64];
__device__ __align__(16) __half g_k[ROWS*64];
__device__ __align__(16) __half g_v[ROWS*64];
__device__ float  g_att[ROWS*64];
__device__ float2 g_part[256];
__device__ float2 g_stats[32];

// ---------------- helpers ----------------
__device__ __forceinline__ unsigned f2tf32(float f){
    unsigned u; asm("cvt.rna.tf32.f32 %0,%1;":"=r"(u):"f"(f)); return u;
}
__device__ __forceinline__ unsigned packh2(float lo,float hi){
    unsigned u; asm("cvt.rn.f16x2.f32 %0,%1,%2;":"=r"(u):"f"(hi),"f"(lo)); return u;
}
__device__ __forceinline__ void mma_h(float* c,unsigned a0,unsigned a1,unsigned a2,unsigned a3,
                                      unsigned b0,unsigned b1){
    asm volatile("mma.sync.aligned.m16n8k16.row.col.f32.f16.f16.f32 "
        "{%0,%1,%2,%3},{%4,%5,%6,%7},{%8,%9},{%0,%1,%2,%3};"
        :"+f"(c[0]),"+f"(c[1]),"+f"(c[2]),"+f"(c[3])
        :"r"(a0),"r"(a1),"r"(a2),"r"(a3),"r"(b0),"r"(b1));
}
__device__ __forceinline__ void mma_t(float* c,unsigned a0,unsigned a1,unsigned a2,unsigned a3,
                                      unsigned b0,unsigned b1){
    asm volatile("mma.sync.aligned.m16n8k8.row.col.f32.tf32.tf32.f32 "
        "{%0,%1,%2,%3},{%4,%5,%6,%7},{%8,%9},{%0,%1,%2,%3};"
        :"+f"(c[0]),"+f"(c[1]),"+f"(c[2]),"+f"(c[3])
        :"r"(a0),"r"(a1),"r"(a2),"r"(a3),"r"(b0),"r"(b1));
}
__device__ __forceinline__ void ldsm4(unsigned&r0,unsigned&r1,unsigned&r2,unsigned&r3,unsigned a){
    asm volatile("ldmatrix.sync.aligned.m8n8.x4.shared.b16 {%0,%1,%2,%3},[%4];"
        :"=r"(r0),"=r"(r1),"=r"(r2),"=r"(r3):"r"(a));
}
__device__ __forceinline__ void ldsm4t(unsigned&r0,unsigned&r1,unsigned&r2,unsigned&r3,unsigned a){
    asm volatile("ldmatrix.sync.aligned.m8n8.x4.trans.shared.b16 {%0,%1,%2,%3},[%4];"
        :"=r"(r0),"=r"(r1),"=r"(r2),"=r"(r3):"r"(a));
}
__device__ __forceinline__ void cp16(unsigned d,const void* s){
    asm volatile("cp.async.cg.shared.global [%0],[%1],16;"::"r"(d),"l"(s));
}

// ---------------------------------------------------------------------------
// 1a/1b. GroupNorm statistics (split + finalize)
// ---------------------------------------------------------------------------
__global__ void gn_stats_part(const float* __restrict__ x){
    __shared__ float ss[256], sq[256];
    const int t = threadIdx.x;
    const float4* base = (const float4*)x + (size_t)blockIdx.x * 1024;
    float s=0.f,q=0.f;
    #pragma unroll
    for(int i=0;i<4;i++){
        float4 v = base[t + i*256];
        s += (v.x+v.y)+(v.z+v.w);
        q += (v.x*v.x+v.y*v.y)+(v.z*v.z+v.w*v.w);
    }
    ss[t]=s; sq[t]=q; __syncthreads();
    for(int st=128;st;st>>=1){ if(t<st){ss[t]+=ss[t+st]; sq[t]+=sq[t+st];} __syncthreads(); }
    if(!t) g_part[blockIdx.x]=make_float2(ss[0],sq[0]);
}
__global__ void gn_stats_final(){
    const int t=threadIdx.x;
    float s=0.f,q=0.f;
    #pragma unroll
    for(int i=0;i<8;i++){ float2 p=g_part[t*8+i]; s+=p.x; q+=p.y; }
    float mean=s*(1.f/32768.f);
    float var =q*(1.f/32768.f)-mean*mean;
    g_stats[t]=make_float2(mean,rsqrtf(var+EPSV));
}

// ---------------------------------------------------------------------------
// 2. Fused GroupNorm-apply + QKV projection (fp16 mma). 128 rows per block.
// ---------------------------------------------------------------------------
__global__ __launch_bounds__(256,1) void qkv_kernel(
        const float* __restrict__ x,
        const float* __restrict__ gamma, const float* __restrict__ beta,
        const float* __restrict__ Wq, const float* __restrict__ bq,
        const float* __restrict__ Wk, const float* __restrict__ bk,
        const float* __restrict__ Wv, const float* __restrict__ bv){
    __shared__ __align__(16) __half sX[128*72];
    __shared__ __align__(16) __half sWt[192*72];
    __shared__ float sB[192];
    const int tid = threadIdx.x;
    const int Rbase = blockIdx.x * 128;

    // weights transposed into smem: sWt[n][c]
    for(int i=tid;i<4096;i+=256){
        int c=i>>6, n=i&63;
        sWt[n*72+c]        = __float2half(Wq[i]);
        sWt[(64+n)*72+c]   = __float2half(Wk[i]);
        sWt[(128+n)*72+c]  = __float2half(Wv[i]);
    }
    if(tid<64){ sB[tid]=bq[tid]; sB[64+tid]=bk[tid]; sB[128+tid]=bv[tid]; }

    // X tile: groupnorm on the fly, half
    {
        int r = tid>>1, cb=(tid&1)*32;
        int R = Rbase + r;
        int h = (R>>6)&63, bi = R>>12;
        float2 st = g_stats[bi*8+(h>>3)];
        float gc = gamma[h]*st.y, bc = beta[h]-st.x*gc;
        const float4* xr = (const float4*)(x + (size_t)R*64 + cb);
        #pragma unroll
        for(int i=0;i<8;i++){
            float4 v = xr[i];
            ((__half2*)&sX[r*72+cb+i*4])[0] = __floats2half2_rn(fmaf(v.x,gc,bc), fmaf(v.y,gc,bc));
            ((__half2*)&sX[r*72+cb+i*4])[1] = __floats2half2_rn(fmaf(v.z,gc,bc), fmaf(v.w,gc,bc));
        }
    }
    __syncthreads();

    const int warp=tid>>5, lane=tid&31, g=lane>>2, t4=lane&3;
    float acc[24][4];
    #pragma unroll
    for(int n=0;n<24;n++) acc[n][0]=acc[n][1]=acc[n][2]=acc[n][3]=0.f;

    #pragma unroll
    for(int kk=0;kk<4;kk++){
        int r0=warp*16+g;
        unsigned a0=*(const unsigned*)&sX[ r0   *72 + kk*16 + 2*t4];
        unsigned a1=*(const unsigned*)&sX[(r0+8)*72 + kk*16 + 2*t4];
        unsigned a2=*(const unsigned*)&sX[ r0   *72 + kk*16 + 2*t4 + 8];
        unsigned a3=*(const unsigned*)&sX[(r0+8)*72 + kk*16 + 2*t4 + 8];
        #pragma unroll
        for(int nt=0;nt<24;nt++){
            unsigned b0=*(const unsigned*)&sWt[(nt*8+g)*72 + kk*16 + 2*t4];
            unsigned b1=*(const unsigned*)&sWt[(nt*8+g)*72 + kk*16 + 2*t4 + 8];
            mma_h(acc[nt],a0,a1,a2,a3,b0,b1);
        }
    }

    int R0 = Rbase + warp*16 + g;
    #pragma unroll
    for(int nt=0;nt<24;nt++){
        int n = nt*8 + 2*t4;
        int col = (nt&7)*8 + 2*t4;
        __half* dst = (nt<8)? g_q : (nt<16)? g_k : g_v;
        float b0f=sB[n], b1f=sB[n+1];
        *(unsigned*)&dst[(size_t)R0*64+col]     = packh2(acc[nt][0]+b0f, acc[nt][1]+b1f);
        *(unsigned*)&dst[(size_t)(R0+8)*64+col] = packh2(acc[nt][2]+b0f, acc[nt][3]+b1f);
    }
}

// ---------------------------------------------------------------------------
// 3. Flash attention, fp16 mma, register-resident softmax, cp.async double buf.
//    Block = 128 queries, 8 warps (one m16 tile each), 64-key tiles.
// ---------------------------------------------------------------------------
__global__ __launch_bounds__(256,1) void attn_kernel(){
    __shared__ __align__(16) __half sK[2][64*SKD];
    __shared__ __align__(16) __half sV[2][64*SKD];

    const int tid=threadIdx.x, warp=tid>>5, lane=tid&31;
    const int g=lane>>2, t4=lane&3, q8=lane>>3, rr=lane&7;
    const int b=blockIdx.x>>5, qbase=(blockIdx.x&31)*128;
    const __half* Qg = g_q + ((size_t)b*NTOK+qbase)*64;
    const __half* Kg = g_k + (size_t)b*NTOK*64;
    const __half* Vg = g_v + (size_t)b*NTOK*64;
    const int r0 = warp*16+g;

    unsigned skb[2], svb[2];
    skb[0]=(unsigned)__cvta_generic_to_shared(&sK[0][0]);
    skb[1]=(unsigned)__cvta_generic_to_shared(&sK[1][0]);
    svb[0]=(unsigned)__cvta_generic_to_shared(&sV[0][0]);
    svb[1]=(unsigned)__cvta_generic_to_shared(&sV[1][0]);

    // Q fragments (half), resident all loop
    unsigned qa[4][4];
    #pragma unroll
    for(int kk=0;kk<4;kk++){
        qa[kk][0]=*(const unsigned*)&Qg[(size_t) r0   *64 + kk*16 + 2*t4];
        qa[kk][1]=*(const unsigned*)&Qg[(size_t)(r0+8)*64 + kk*16 + 2*t4];
        qa[kk][2]=*(const unsigned*)&Qg[(size_t) r0   *64 + kk*16 + 2*t4 + 8];
        qa[kk][3]=*(const unsigned*)&Qg[(size_t)(r0+8)*64 + kk*16 + 2*t4 + 8];
    }
    float o[8][4];
    #pragma unroll
    for(int n=0;n<8;n++) o[n][0]=o[n][1]=o[n][2]=o[n][3]=0.f;
    float m0=-1e30f, m1=-1e30f, l0=0.f, l1=0.f;

    // tile issue: 64 rows x 64 halves (128B) per matrix, 2 chunks/thread each
    auto issue = [&](int kt,int buf){
        const __half* ks = Kg + (size_t)kt*64*64;
        const __half* vs = Vg + (size_t)kt*64*64;
        #pragma unroll
        for(int i=0;i<2;i++){
            int idx = tid + i*256;
            int row = idx>>3, c=(idx&7)*8;
            cp16(skb[buf] + (row*SKD+c)*2, ks + row*64 + c);
            cp16(svb[buf] + (row*SKD+c)*2, vs + row*64 + c);
        }
    };
    issue(0,0);
    asm volatile("cp.async.commit_group;");

    for(int kt=0;kt<64;kt++){
        const int cur=kt&1;
        if(kt<63){
            issue(kt+1,cur^1);
            asm volatile("cp.async.commit_group;");
            asm volatile("cp.async.wait_group 1;");
        } else {
            asm volatile("cp.async.wait_group 0;");
        }
        __syncthreads();

        // ---- S = Q @ K^T ----
        float s[8][4];
        #pragma unroll
        for(int n=0;n<8;n++) s[n][0]=s[n][1]=s[n][2]=s[n][3]=0.f;
        #pragma unroll
        for(int kk=0;kk<4;kk++){
            #pragma unroll
            for(int np=0;np<4;np++){
                unsigned b00,b01,b10,b11;
                unsigned a = skb[cur] + (((np*16 + (q8>>1)*8 + rr)*SKD) + kk*16 + (q8&1)*8)*2;
                ldsm4(b00,b01,b10,b11,a);
                mma_h(s[2*np  ], qa[kk][0],qa[kk][1],qa[kk][2],qa[kk][3], b00,b01);
                mma_h(s[2*np+1], qa[kk][0],qa[kk][1],qa[kk][2],qa[kk][3], b10,b11);
            }
        }

        // ---- online softmax (register-resident; quad = lanes sharing g) ----
        float mx0=-1e30f, mx1=-1e30f;
        #pragma unroll
        for(int n=0;n<8;n++){
            s[n][0]*=SC_L2E; s[n][1]*=SC_L2E; s[n][2]*=SC_L2E; s[n][3]*=SC_L2E;
            mx0=fmaxf(mx0,fmaxf(s[n][0],s[n][1]));
            mx1=fmaxf(mx1,fmaxf(s[n][2],s[n][3]));
        }
        mx0=fmaxf(mx0,__shfl_xor_sync(0xffffffffu,mx0,1));
        mx0=fmaxf(mx0,__shfl_xor_sync(0xffffffffu,mx0,2));
        mx1=fmaxf(mx1,__shfl_xor_sync(0xffffffffu,mx1,1));
        mx1=fmaxf(mx1,__shfl_xor_sync(0xffffffffu,mx1,2));
        float mn0=fmaxf(m0,mx0), mn1=fmaxf(m1,mx1);
        float c0=exp2f(m0-mn0), c1=exp2f(m1-mn1);
        float ls0=0.f, ls1=0.f;
        unsigned pa0[8], pa1[8];
        #pragma unroll
        for(int n=0;n<8;n++){
            float p00=exp2f(s[n][0]-mn0), p01=exp2f(s[n][1]-mn0);
            float p10=exp2f(s[n][2]-mn1), p11=exp2f(s[n][3]-mn1);
            ls0+=p00+p01; ls1+=p10+p11;
            pa0[n]=packh2(p00,p01); pa1[n]=packh2(p10,p11);
        }
        l0=l0*c0+ls0; l1=l1*c1+ls1; m0=mn0; m1=mn1;
        #pragma unroll
        for(int n=0;n<8;n++){ o[n][0]*=c0; o[n][1]*=c0; o[n][2]*=c1; o[n][3]*=c1; }

        // ---- O += P @ V ----
        #pragma unroll
        for(int kk=0;kk<4;kk++){
            unsigned a0=pa0[2*kk], a1=pa1[2*kk], a2=pa0[2*kk+1], a3=pa1[2*kk+1];
            #pragma unroll
            for(int np=0;np<4;np++){
                unsigned b00,b01,b10,b11;
                unsigned a = svb[cur] + (((kk*16 + (q8&1)*8 + rr)*SKD) + np*16 + (q8>>1)*8)*2;
                ldsm4t(b00,b01,b10,b11,a);
                mma_h(o[2*np  ], a0,a1,a2,a3, b00,b01);
                mma_h(o[2*np+1], a0,a1,a2,a3, b10,b11);
            }
        }
        __syncthreads();
    }

    l0+=__shfl_xor_sync(0xffffffffu,l0,1); l0+=__shfl_xor_sync(0xffffffffu,l0,2);
    l1+=__shfl_xor_sync(0xffffffffu,l1,1); l1+=__shfl_xor_sync(0xffffffffu,l1,2);
    float i0=1.f/l0, i1=1.f/l1;
    float* Og = g_att + ((size_t)b*NTOK+qbase)*64;
    #pragma unroll
    for(int n=0;n<8;n++){
        *(float2*)&Og[(size_t) r0   *64 + n*8 + 2*t4] = make_float2(o[n][0]*i0, o[n][1]*i0);
        *(float2*)&Og[(size_t)(r0+8)*64 + n*8 + 2*t4] = make_float2(o[n][2]*i1, o[n][3]*i1);
    }
}

// ---------------------------------------------------------------------------
// 4. Output projection (tf32 mma) + recomputed-GN residual: out = xn + att@Wo + bo
// ---------------------------------------------------------------------------
__global__ __launch_bounds__(256,1) void final_kernel(
        const float* __restrict__ x,
        const float* __restrict__ gamma, const float* __restrict__ beta,
        const float* __restrict__ Wo, const float* __restrict__ bo,
        float* __restrict__ out){
    extern __shared__ float sm[];
    float* sA  = sm;                // 128*68
    float* sWt = sm + 128*68;       // 64*68
    float* sB  = sWt + 64*68;       // 64
    const int tid=threadIdx.x;
    const int Rbase = blockIdx.x*128;

    for(int i=tid;i<4096;i+=256){
        int c=i>>6, n=i&63;
        sWt[n*68+c] = __uint_as_float(f2tf32(Wo[i]));
    }
    if(tid<64) sB[tid]=bo[tid];
    {
        int r=tid>>1, cb=(tid&1)*32;
        const float4* ar=(const float4*)(g_att+(size_t)(Rbase+r)*64+cb);
        #pragma unroll
        for(int i=0;i<8;i++){
            float4 v=ar[i];
            sA[r*68+cb+i*4+0]=__uint_as_float(f2tf32(v.x));
            sA[r*68+cb+i*4+1]=__uint_as_float(f2tf32(v.y));
            sA[r*68+cb+i*4+2]=__uint_as_float(f2tf32(v.z));
            sA[r*68+cb+i*4+3]=__uint_as_float(f2tf32(v.w));
        }
    }
    __syncthreads();

    const int warp=tid>>5, lane=tid&31, g=lane>>2, t4=lane&3;
    float acc[8][4];
    #pragma unroll
    for(int n=0;n<8;n++) acc[n][0]=acc[n][1]=acc[n][2]=acc[n][3]=0.f;

    #pragma unroll
    for(int kk=0;kk<8;kk++){
        int r0=warp*16+g;
        unsigned a0=__float_as_uint(sA[ r0   *68 + kk*8 + t4]);
        unsigned a1=__float_as_uint(sA[(r0+8)*68 + kk*8 + t4]);
        unsigned a2=__float_as_uint(sA[ r0   *68 + kk*8 + t4 + 4]);
        unsigned a3=__float_as_uint(sA[(r0+8)*68 + kk*8 + t4 + 4]);
        #pragma unroll
        for(int nt=0;nt<8;nt++){
            unsigned b0=__float_as_uint(sWt[(nt*8+g)*68 + kk*8 + t4]);
            unsigned b1=__float_as_uint(sWt[(nt*8+g)*68 + kk*8 + t4 + 4]);
            mma_t(acc[nt],a0,a1,a2,a3,b0,b1);
        }
    }

    int R0 = Rbase + warp*16 + g;
    int h=(R0>>6)&63, bi=R0>>12;
    float2 st=g_stats[bi*8+(h>>3)];
    float gc=gamma[h]*st.y, bc=beta[h]-st.x*gc;
    #pragma unroll
    for(int nt=0;nt<8;nt++){
        int col=nt*8+2*t4;
        float2 x0=*(const float2*)&x[(size_t)R0*64+col];
        float2 x1=*(const float2*)&x[(size_t)(R0+8)*64+col];
        float2 r0v, r1v;
        r0v.x=fmaf(x0.x,gc,bc)+acc[nt][0]+sB[col];
        r0v.y=fmaf(x0.y,gc,bc)+acc[nt][1]+sB[col+1];
        r1v.x=fmaf(x1.x,gc,bc)+acc[nt][2]+sB[col];
        r1v.y=fmaf(x1.y,gc,bc)+acc[nt][3]+sB[col+1];
        *(float2*)&out[(size_t)R0*64+col]=r0v;
        *(float2*)&out[(size_t)(R0+8)*64+col]=r1v;
    }
}

// ---------------------------------------------------------------------------
extern "C" void kernel_launch(void* const* d_in, const int* in_sizes, int n_in,
                              void* d_out, int out_size) {
    const float* x     = (const float*)d_in[0];
    const float* gamma = (const float*)d_in[1];
    const float* beta  = (const float*)d_in[2];
    const float* Wq    = (const float*)d_in[3];
    const float* bq    = (const float*)d_in[4];
    const float* Wk    = (const float*)d_in[5];
    const float* bk    = (const float*)d_in[6];
    const float* Wv    = (const float*)d_in[7];
    const float* bv    = (const float*)d_in[8];
    const float* Wo    = (const float*)d_in[9];
    const float* bo    = (const float*)d_in[10];
    float* out = (float*)d_out;

    const int final_smem = (128*68 + 64*68 + 64)*4;   // 52480 B
    cudaFuncSetAttribute(final_kernel, cudaFuncAttributeMaxDynamicSharedMemorySize, final_smem);

    gn_stats_part<<<256,256>>>(x);
    gn_stats_final<<<1,32>>>();
    qkv_kernel<<<128,256>>>(x, gamma, beta, Wq, bq, Wk, bk, Wv, bv);
    attn_kernel<<<128,256>>>();
    final_kernel<<<128,256,final_smem>>>(x, gamma, beta, Wo, bo, out);
}